// round 1
// baseline (speedup 1.0000x reference)
#include <cuda_runtime.h>
#include <stdint.h>

#define NQ      8
#define NPAIRS  28
#define NB      16384
#define THREADS 128

// Pre-computed cos/sin of vqc theta/2 (batch-shared): [layer*8 + qubit]
__device__ float2 g_vqc_cs[2 * NQ];

__global__ void precompute_vqc(const float* __restrict__ w) {
    int i = threadIdx.x;
    if (i < 2 * NQ) {
        float th = w[i * 3 + 1];
        float c, s;
        __sincosf(0.5f * th, &s, &c);
        g_vqc_cs[i] = make_float2(c, s);
    }
}

// ---------------- gate primitives ----------------
// State layout: s = lane*8 + r. Qubit k has bit position bp = 7-k in s.
// bp in [3,7] -> lane bit (bp-3); bp in [0,2] -> register bit of r.

template<int K>
__device__ __forceinline__ void ry_gate(float2 (&a)[8], float c, float s, unsigned lane) {
    constexpr int bp = 7 - K;
    if constexpr (bp >= 3) {
        constexpr int lm = 1 << (bp - 3);
        const float sg = (lane & lm) ? s : -s;   // bit==1 row: s*a0 + c*a1
#pragma unroll
        for (int r = 0; r < 8; r++) {
            float px = __shfl_xor_sync(0xffffffffu, a[r].x, lm);
            float py = __shfl_xor_sync(0xffffffffu, a[r].y, lm);
            a[r].x = fmaf(sg, px, c * a[r].x);
            a[r].y = fmaf(sg, py, c * a[r].y);
        }
    } else {
        constexpr int m = 1 << bp;
#pragma unroll
        for (int r = 0; r < 8; r++) {
            if (!(r & m)) {
                float2 x = a[r], y = a[r | m];
                a[r].x     = fmaf(-s, y.x, c * x.x);
                a[r].y     = fmaf(-s, y.y, c * x.y);
                a[r | m].x = fmaf( s, x.x, c * y.x);
                a[r | m].y = fmaf( s, x.y, c * y.y);
            }
        }
    }
}

template<int K>
__device__ __forceinline__ void ry_all(float2 (&a)[8], const float (&c)[8],
                                       const float (&s)[8], unsigned lane) {
    if constexpr (K < 8) {
        ry_gate<K>(a, c[K], s[K], lane);
        ry_all<K + 1>(a, c, s, lane);
    }
}

template<int CTRL, int TGT>
__device__ __forceinline__ void cnot_gate(float2 (&a)[8], unsigned lane) {
    constexpr int CB = 7 - CTRL, TB = 7 - TGT;
    if constexpr (TB >= 3) {
        constexpr int lm = 1 << (TB - 3);
        if constexpr (CB >= 3) {
            const bool cs = (lane >> (CB - 3)) & 1;
#pragma unroll
            for (int r = 0; r < 8; r++) {
                float px = __shfl_xor_sync(0xffffffffu, a[r].x, lm);
                float py = __shfl_xor_sync(0xffffffffu, a[r].y, lm);
                a[r].x = cs ? px : a[r].x;
                a[r].y = cs ? py : a[r].y;
            }
        } else {
#pragma unroll
            for (int r = 0; r < 8; r++) {
                if ((r >> CB) & 1) {   // compile-time predicate: uniform across warp
                    a[r].x = __shfl_xor_sync(0xffffffffu, a[r].x, lm);
                    a[r].y = __shfl_xor_sync(0xffffffffu, a[r].y, lm);
                }
            }
        }
    } else {
        constexpr int m = 1 << TB;
        if constexpr (CB >= 3) {
            const bool cs = (lane >> (CB - 3)) & 1;
#pragma unroll
            for (int r = 0; r < 8; r++) {
                if (!(r & m)) {
                    float2 t0 = a[r], t1 = a[r | m];
                    a[r].x = cs ? t1.x : t0.x;  a[r].y = cs ? t1.y : t0.y;
                    a[r | m].x = cs ? t0.x : t1.x;  a[r | m].y = cs ? t0.y : t1.y;
                }
            }
        } else {
#pragma unroll
            for (int r = 0; r < 8; r++) {
                if (((r >> CB) & 1) && !((r >> TB) & 1)) {
                    float2 t = a[r]; a[r] = a[r | m]; a[r | m] = t;
                }
            }
        }
    }
}

template<int K, int RNG>
__device__ __forceinline__ void cnot_ring(float2 (&a)[8], unsigned lane) {
    if constexpr (K < 8) {
        cnot_gate<K, (K + RNG) % 8>(a, lane);
        cnot_ring<K + 1, RNG>(a, lane);
    }
}

// Merged diagonal: phase(s) = sum_k (bit_k(s) ? +hc[k] : -hc[k]) [+ extra_r]
template<bool HAS_EXTRA>
__device__ __forceinline__ void diag_gate(float2 (&a)[8], const float (&hc)[8],
                                          const float (&extra)[8], unsigned lane) {
    float base = 0.f;
#pragma unroll
    for (int k = 0; k < 5; k++)
        base += ((lane >> (4 - k)) & 1) ? hc[k] : -hc[k];
#pragma unroll
    for (int r = 0; r < 8; r++) {
        float phr = base;
#pragma unroll
        for (int k = 5; k < 8; k++)
            phr += ((r >> (7 - k)) & 1) ? hc[k] : -hc[k];
        if constexpr (HAS_EXTRA) phr += extra[r];
        // range-reduce: __sincosf accuracy degrades for |x| >> pi (Ising phases ~ +-30)
        float q = rintf(phr * 0.15915494309189535f);
        phr = fmaf(q, -6.2831855f, phr);
        float cc, ss;
        __sincosf(phr, &ss, &cc);
        float x = a[r].x, y = a[r].y;
        a[r].x = fmaf(cc, x, -ss * y);
        a[r].y = fmaf(cc, y,  ss * x);
    }
}

// ---------------- main kernel ----------------

__global__ void __launch_bounds__(THREADS)
vqc_kernel(const float* __restrict__ theta, const float* __restrict__ phi,
           const float* __restrict__ jup, const float* __restrict__ w,
           float* __restrict__ out) {
    const unsigned tid  = blockIdx.x * THREADS + threadIdx.x;
    const unsigned b    = tid >> 5;
    const unsigned lane = tid & 31;

    // per-batch angles (warp-uniform loads; L1 broadcast)
    float ph[NQ];
    float cq[NQ], sq[NQ];   // cos/sin(theta/4)  (re-encode RY half-angle)
    float ch[NQ], sh[NQ];   // cos/sin(theta/2)  (encoding RY half-angle) via double-angle
#pragma unroll
    for (int k = 0; k < NQ; k++) {
        float th = theta[b * NQ + k];
        ph[k] = phi[b * NQ + k];
        __sincosf(0.25f * th, &sq[k], &cq[k]);
        sh[k] = 2.f * sq[k] * cq[k];
        ch[k] = fmaf(-2.f * sq[k], sq[k], 1.f);
    }

    // state |0...0>
    float2 a[8];
#pragma unroll
    for (int r = 0; r < 8; r++) a[r] = make_float2(0.f, 0.f);
    if (lane == 0) a[0].x = 1.f;

    float dummy[8];

    // ===== encoding RY(theta) =====
    ry_all<0>(a, ch, sh, lane);

    // ===== DIAG1: encoding RZ(phi) + IsingZZ + layer0 Rot-RZ(phi_w) =====
    float exr[8];
    {
        float il = 0.f, U0 = 0.f, U1 = 0.f, U2 = 0.f;
        float J56 = 0.f, J57 = 0.f, J67 = 0.f;
        int p = 0;
#pragma unroll
        for (int i = 0; i < 8; i++) {
#pragma unroll
            for (int j = i + 1; j < 8; j++) {
                float J = jup[(size_t)b * NPAIRS + p];
                if (j < 5) {                       // lane-lane pair
                    int d = ((lane >> (4 - i)) ^ (lane >> (4 - j))) & 1;
                    il += d ? J : -J;
                } else if (i < 5) {                // lane-reg pair
                    int bi = (lane >> (4 - i)) & 1;
                    float v = bi ? J : -J;
                    if (j == 5) U0 += v; else if (j == 6) U1 += v; else U2 += v;
                } else {                           // reg-reg pair
                    if (i == 5 && j == 6) J56 = J;
                    else if (i == 5 && j == 7) J57 = J;
                    else J67 = J;
                }
                p++;
            }
        }
#pragma unroll
        for (int r = 0; r < 8; r++) {
            int b5 = (r >> 2) & 1, b6 = (r >> 1) & 1, b7 = r & 1;
            float e = il;
            e += b5 ? -U0 : U0;
            e += b6 ? -U1 : U1;
            e += b7 ? -U2 : U2;
            e += (b5 ^ b6) ? J56 : -J56;
            e += (b5 ^ b7) ? J57 : -J57;
            e += (b6 ^ b7) ? J67 : -J67;
            exr[r] = 1.5707963267948966f * e;
        }
    }
    {
        float hc[8];
#pragma unroll
        for (int k = 0; k < NQ; k++)
            hc[k] = 0.5f * (ph[k] + w[k * 3 + 0]);
        diag_gate<true>(a, hc, exr, lane);
    }

    // ===== layer 0: Rot RY =====
    {
        float c[8], s[8];
#pragma unroll
        for (int k = 0; k < NQ; k++) { float2 cs = g_vqc_cs[k]; c[k] = cs.x; s[k] = cs.y; }
        ry_all<0>(a, c, s, lane);
    }
    // DIAG2: layer0 Rot-RZ(omega)
    {
        float hc[8];
#pragma unroll
        for (int k = 0; k < NQ; k++) hc[k] = 0.5f * w[k * 3 + 2];
        diag_gate<false>(a, hc, dummy, lane);
    }
    // CNOT ring, range 1
    cnot_ring<0, 1>(a, lane);

    // ===== re-encode RY(theta/2) =====
    ry_all<0>(a, cq, sq, lane);

    // DIAG3: re-encode RZ(phi/2) + layer1 Rot-RZ(phi_w)
    {
        float hc[8];
#pragma unroll
        for (int k = 0; k < NQ; k++)
            hc[k] = fmaf(0.25f, ph[k], 0.5f * w[(8 + k) * 3 + 0]);
        diag_gate<false>(a, hc, dummy, lane);
    }

    // ===== layer 1: Rot RY =====
    {
        float c[8], s[8];
#pragma unroll
        for (int k = 0; k < NQ; k++) { float2 cs = g_vqc_cs[8 + k]; c[k] = cs.x; s[k] = cs.y; }
        ry_all<0>(a, c, s, lane);
    }
    // DIAG4: layer1 Rot-RZ(omega)
    {
        float hc[8];
#pragma unroll
        for (int k = 0; k < NQ; k++) hc[k] = 0.5f * w[(8 + k) * 3 + 2];
        diag_gate<false>(a, hc, dummy, lane);
    }
    // CNOT ring, range 2
    cnot_ring<0, 2>(a, lane);

    // ===== expectations <Z_k> =====
    float pr[8], ptot = 0.f;
#pragma unroll
    for (int r = 0; r < 8; r++) {
        pr[r] = fmaf(a[r].x, a[r].x, a[r].y * a[r].y);
        ptot += pr[r];
    }
    float ez[8];
#pragma unroll
    for (int k = 0; k < 5; k++)
        ez[k] = ((lane >> (4 - k)) & 1) ? -ptot : ptot;
#pragma unroll
    for (int k = 5; k < 8; k++) {
        float s = 0.f;
#pragma unroll
        for (int r = 0; r < 8; r++)
            s += ((r >> (7 - k)) & 1) ? -pr[r] : pr[r];
        ez[k] = s;
    }
#pragma unroll
    for (int k = 0; k < 8; k++) {
#pragma unroll
        for (int off = 16; off > 0; off >>= 1)
            ez[k] += __shfl_xor_sync(0xffffffffu, ez[k], off);
    }
    if (lane == 0) {
        float4* o = reinterpret_cast<float4*>(out + (size_t)b * NQ);
        o[0] = make_float4(ez[0], ez[1], ez[2], ez[3]);
        o[1] = make_float4(ez[4], ez[5], ez[6], ez[7]);
    }
}

extern "C" void kernel_launch(void* const* d_in, const int* in_sizes, int n_in,
                              void* d_out, int out_size) {
    const float* theta = (const float*)d_in[0];
    const float* phi   = (const float*)d_in[1];
    const float* jup   = (const float*)d_in[2];
    const float* w     = (const float*)d_in[3];
    float* out = (float*)d_out;

    precompute_vqc<<<1, 32>>>(w);
    const int grid = (NB * 32) / THREADS;   // one warp per batch element
    vqc_kernel<<<grid, THREADS>>>(theta, phi, jup, w, out);
}

// round 2
// speedup vs baseline: 1.1014x; 1.1014x over previous
#include <cuda_runtime.h>
#include <stdint.h>

#define NQ      8
#define NPAIRS  28
#define NB      16384
#define THREADS 128

typedef unsigned long long u64;

// batch-shared precomputed constants
__device__ float2 g_vqc_cs[2 * NQ];   // cos/sin(theta_w/2) per (layer,qubit)
__device__ float  g_hw[4][NQ];        // 0.5*phi_w(l0), 0.5*omega_w(l0), 0.5*phi_w(l1), 0.5*omega_w(l1)

__global__ void precompute_vqc(const float* __restrict__ w) {
    int i = threadIdx.x;
    if (i < 2 * NQ) {
        float th = w[i * 3 + 1];
        float c, s;
        __sincosf(0.5f * th, &s, &c);
        g_vqc_cs[i] = make_float2(c, s);
    }
    if (i < NQ) {
        g_hw[0][i] = 0.5f * w[i * 3 + 0];
        g_hw[1][i] = 0.5f * w[i * 3 + 2];
        g_hw[2][i] = 0.5f * w[(NQ + i) * 3 + 0];
        g_hw[3][i] = 0.5f * w[(NQ + i) * 3 + 2];
    }
}

// ---------------- f32x2 packed helpers ----------------
__device__ __forceinline__ u64 pk(float lo, float hi) {
    u64 v; asm("mov.b64 %0, {%1, %2};" : "=l"(v) : "f"(lo), "f"(hi)); return v;
}
__device__ __forceinline__ void upk(u64 v, float& lo, float& hi) {
    asm("mov.b64 {%0, %1}, %2;" : "=f"(lo), "=f"(hi) : "l"(v));
}
__device__ __forceinline__ u64 bc2(float x) { return pk(x, x); }
__device__ __forceinline__ u64 fma2(u64 a, u64 b, u64 c) {
    u64 d; asm("fma.rn.f32x2 %0, %1, %2, %3;" : "=l"(d) : "l"(a), "l"(b), "l"(c)); return d;
}
__device__ __forceinline__ u64 mul2(u64 a, u64 b) {
    u64 d; asm("mul.rn.f32x2 %0, %1, %2;" : "=l"(d) : "l"(a), "l"(b)); return d;
}
__device__ __forceinline__ u64 shflx2(u64 v, int m) {
    float lo, hi; upk(v, lo, hi);
    lo = __shfl_xor_sync(0xffffffffu, lo, m);
    hi = __shfl_xor_sync(0xffffffffu, hi, m);
    return pk(lo, hi);
}
__device__ __forceinline__ u64 shfli2(u64 v, int src) {
    float lo, hi; upk(v, lo, hi);
    lo = __shfl_sync(0xffffffffu, lo, src);
    hi = __shfl_sync(0xffffffffu, hi, src);
    return pk(lo, hi);
}

// ---------------- gate primitives ----------------
// State: s = lane*8 + r. Qubit k -> bit position bp = 7-k of s.
// bp in [3,7]: lane bit (bp-3); bp in [0,2]: register-index bit of r.

template<int K>
__device__ __forceinline__ void ry_gate(u64 (&a)[8], float c, float s, unsigned lane) {
    constexpr int bp = 7 - K;
    const u64 c2 = bc2(c);
    if constexpr (bp >= 3) {
        constexpr int lm = 1 << (bp - 3);
        const u64 sg2 = bc2((lane & lm) ? s : -s);
#pragma unroll
        for (int r = 0; r < 8; r++) {
            u64 p = shflx2(a[r], lm);
            a[r] = fma2(sg2, p, mul2(c2, a[r]));
        }
    } else {
        constexpr int m = 1 << bp;
        const u64 s2 = bc2(s), ns2 = bc2(-s);
#pragma unroll
        for (int r = 0; r < 8; r++) {
            if (!(r & m)) {
                u64 x = a[r], y = a[r | m];
                a[r]     = fma2(ns2, y, mul2(c2, x));
                a[r | m] = fma2(s2,  x, mul2(c2, y));
            }
        }
    }
}

template<int K>
__device__ __forceinline__ void ry_all(u64 (&a)[8], const float (&c)[8],
                                       const float (&s)[8], unsigned lane) {
    if constexpr (K < 8) {
        ry_gate<K>(a, c[K], s[K], lane);
        ry_all<K + 1>(a, c, s, lane);
    }
}

template<int CTRL, int TGT>
__device__ __forceinline__ void cnot_gate(u64 (&a)[8], unsigned lane) {
    constexpr int CB = 7 - CTRL, TB = 7 - TGT;
    if constexpr (TB >= 3) {
        constexpr int lm = 1 << (TB - 3);
        if constexpr (CB >= 3) {
            // lane ctrl, lane target: pure lane permutation via idx-shuffle
            const int src = (int)(lane ^ (((lane >> (CB - 3)) & 1u) ? lm : 0u));
#pragma unroll
            for (int r = 0; r < 8; r++) a[r] = shfli2(a[r], src);
        } else {
            // reg ctrl, lane target: xor-shuffle only regs with ctrl bit set
#pragma unroll
            for (int r = 0; r < 8; r++)
                if ((r >> CB) & 1) a[r] = shflx2(a[r], lm);
        }
    } else {
        constexpr int m = 1 << TB;
        if constexpr (CB >= 3) {
            const bool cs = (lane >> (CB - 3)) & 1;
#pragma unroll
            for (int r = 0; r < 8; r++) {
                if (!(r & m)) {
                    u64 t0 = a[r], t1 = a[r | m];
                    a[r]     = cs ? t1 : t0;
                    a[r | m] = cs ? t0 : t1;
                }
            }
        } else {
#pragma unroll
            for (int r = 0; r < 8; r++) {
                if (((r >> CB) & 1) && !((r >> TB) & 1)) {
                    u64 t = a[r]; a[r] = a[r | m]; a[r | m] = t;
                }
            }
        }
    }
}

template<int K, int RNG>
__device__ __forceinline__ void cnot_ring(u64 (&a)[8], unsigned lane) {
    if constexpr (K < 8) {
        cnot_gate<K, (K + RNG) % 8>(a, lane);
        cnot_ring<K + 1, RNG>(a, lane);
    }
}

// Merged diagonal. phase(s) = sum_k (bit_k(s)? +hc[k] : -hc[k]) [+ extra_r]
// Reg-bit part evaluated via 3-stage Walsh-Hadamard butterfly.
template<bool HAS_EXTRA>
__device__ __forceinline__ void diag_gate(u64 (&a)[8], const float (&hc)[8],
                                          const float (&extra)[8], unsigned lane) {
    float base = 0.f;
#pragma unroll
    for (int k = 0; k < 5; k++)
        base += ((lane >> (4 - k)) & 1) ? hc[k] : -hc[k];
    // Walsh coefficients over r-bits (b5<->4, b6<->2, b7<->1): chi_k coeff = -hc[k]
    float w0[8] = { base, -hc[7], -hc[6], 0.f, -hc[5], 0.f, 0.f, 0.f };
#pragma unroll
    for (int st = 1; st < 8; st <<= 1) {
#pragma unroll
        for (int i = 0; i < 8; i++) {
            if (!(i & st)) {
                float u = w0[i], v = w0[i | st];
                w0[i] = u + v; w0[i | st] = u - v;
            }
        }
    }
#pragma unroll
    for (int r = 0; r < 8; r++) {
        float phr = w0[r];
        if constexpr (HAS_EXTRA) phr += extra[r];
        float q = rintf(phr * 0.15915494309189535f);
        phr = fmaf(q, -6.2831855f, phr);
        float cc, ss;
        __sincosf(phr, &ss, &cc);
        float x, y; upk(a[r], x, y);
        float nx = fmaf(cc, x, -ss * y);
        float ny = fmaf(cc, y,  ss * x);
        a[r] = pk(nx, ny);
    }
}

// ---------------- main kernel ----------------

__global__ void __launch_bounds__(THREADS)
vqc_kernel(const float* __restrict__ theta, const float* __restrict__ phi,
           const float* __restrict__ jup, const float* __restrict__ w,
           float* __restrict__ out) {
    const unsigned tid  = blockIdx.x * THREADS + threadIdx.x;
    const unsigned b    = tid >> 5;
    const unsigned lane = tid & 31;

    float ph[NQ];
    float cq[NQ], sq[NQ];   // cos/sin(theta/4)  (re-encode)
    float ch[NQ], sh[NQ];   // cos/sin(theta/2)  (encode) via double-angle
#pragma unroll
    for (int k = 0; k < NQ; k++) {
        float th = theta[b * NQ + k];
        ph[k] = phi[b * NQ + k];
        __sincosf(0.25f * th, &sq[k], &cq[k]);
        sh[k] = 2.f * sq[k] * cq[k];
        ch[k] = fmaf(-2.f * sq[k], sq[k], 1.f);
    }

    // state |0...0>
    u64 a[8];
#pragma unroll
    for (int r = 0; r < 8; r++) a[r] = 0ull;
    if (lane == 0) a[0] = pk(1.f, 0.f);

    float dummy[8];

    // ===== encoding RY(theta) =====
    ry_all<0>(a, ch, sh, lane);

    // ===== Ising phase table exr[r] via WHT butterfly =====
    float exr[8];
    {
        const float HP = 1.5707963267948966f;
        float il = 0.f, U0 = 0.f, U1 = 0.f, U2 = 0.f;
        float J56 = 0.f, J57 = 0.f, J67 = 0.f;
        int p = 0;
#pragma unroll
        for (int i = 0; i < 8; i++) {
#pragma unroll
            for (int j = i + 1; j < 8; j++) {
                float J = jup[(size_t)b * NPAIRS + p];
                if (j < 5) {
                    int d = ((lane >> (4 - i)) ^ (lane >> (4 - j))) & 1;
                    il += d ? J : -J;
                } else if (i < 5) {
                    int bi = (lane >> (4 - i)) & 1;
                    float v = bi ? J : -J;
                    if (j == 5) U0 += v; else if (j == 6) U1 += v; else U2 += v;
                } else {
                    if (i == 5 && j == 6) J56 = J;
                    else if (i == 5 && j == 7) J57 = J;
                    else J67 = J;
                }
                p++;
            }
        }
        float wI[8] = { il * HP,  U2 * HP,  U1 * HP, -J67 * HP,
                        U0 * HP, -J57 * HP, -J56 * HP, 0.f };
#pragma unroll
        for (int st = 1; st < 8; st <<= 1) {
#pragma unroll
            for (int i = 0; i < 8; i++) {
                if (!(i & st)) {
                    float u = wI[i], v = wI[i | st];
                    wI[i] = u + v; wI[i | st] = u - v;
                }
            }
        }
#pragma unroll
        for (int r = 0; r < 8; r++) exr[r] = wI[r];
    }

    // ===== DIAG1: encoding RZ(phi) + Ising + layer0 Rot-RZ(phi_w) =====
    {
        float hc[8];
#pragma unroll
        for (int k = 0; k < NQ; k++) hc[k] = fmaf(0.5f, ph[k], g_hw[0][k]);
        diag_gate<true>(a, hc, exr, lane);
    }

    // ===== layer 0 Rot-RY =====
    {
        float c[8], s[8];
#pragma unroll
        for (int k = 0; k < NQ; k++) { float2 cs = g_vqc_cs[k]; c[k] = cs.x; s[k] = cs.y; }
        ry_all<0>(a, c, s, lane);
    }
    // DIAG2: layer0 Rot-RZ(omega)
    {
        float hc[8];
#pragma unroll
        for (int k = 0; k < NQ; k++) hc[k] = g_hw[1][k];
        diag_gate<false>(a, hc, dummy, lane);
    }
    cnot_ring<0, 1>(a, lane);

    // ===== re-encode RY(theta/2) =====
    ry_all<0>(a, cq, sq, lane);

    // DIAG3: re-encode RZ(phi/2) + layer1 Rot-RZ(phi_w)
    {
        float hc[8];
#pragma unroll
        for (int k = 0; k < NQ; k++) hc[k] = fmaf(0.25f, ph[k], g_hw[2][k]);
        diag_gate<false>(a, hc, dummy, lane);
    }

    // ===== layer 1 Rot-RY =====
    {
        float c[8], s[8];
#pragma unroll
        for (int k = 0; k < NQ; k++) { float2 cs = g_vqc_cs[NQ + k]; c[k] = cs.x; s[k] = cs.y; }
        ry_all<0>(a, c, s, lane);
    }
    // DIAG4: layer1 Rot-RZ(omega)
    {
        float hc[8];
#pragma unroll
        for (int k = 0; k < NQ; k++) hc[k] = g_hw[3][k];
        diag_gate<false>(a, hc, dummy, lane);
    }
    cnot_ring<0, 2>(a, lane);

    // ===== expectations =====
    // per-thread: prob per reg, then WHT over reg bits gives (ptot, s5, s6, s7)
    float pw[8];
#pragma unroll
    for (int r = 0; r < 8; r++) {
        float x, y; upk(a[r], x, y);
        pw[r] = fmaf(x, x, y * y);
    }
#pragma unroll
    for (int st = 1; st < 8; st <<= 1) {
#pragma unroll
        for (int i = 0; i < 8; i++) {
            if (!(i & st)) {
                float u = pw[i], v = pw[i | st];
                pw[i] = u + v; pw[i | st] = u - v;
            }
        }
    }
    float ptot = pw[0], s5 = pw[4], s6 = pw[2], s7 = pw[1];

    // lane WHT on ptot: after 5 steps, lane j holds sum_l (-1)^{popc(j&l)} ptot_l.
    // ez[k] (k<5) lives in lane 2^(4-k).
#pragma unroll
    for (int m = 1; m < 32; m <<= 1) {
        float t = __shfl_xor_sync(0xffffffffu, ptot, m);
        ptot = (lane & m) ? (t - ptot) : (ptot + t);
    }
    // plain butterfly sums for reg-qubit expectations
#pragma unroll
    for (int m = 1; m < 32; m <<= 1) {
        s5 += __shfl_xor_sync(0xffffffffu, s5, m);
        s6 += __shfl_xor_sync(0xffffffffu, s6, m);
        s7 += __shfl_xor_sync(0xffffffffu, s7, m);
    }

    float* ob = out + (size_t)b * NQ;
    if (__popc(lane) == 1 && lane <= 16)
        ob[5 - __ffs(lane)] = ptot;           // lanes 16,8,4,2,1 -> ez[0..4]
    if (lane == 0) { ob[5] = s5; ob[6] = s6; ob[7] = s7; }
}

extern "C" void kernel_launch(void* const* d_in, const int* in_sizes, int n_in,
                              void* d_out, int out_size) {
    const float* theta = (const float*)d_in[0];
    const float* phi   = (const float*)d_in[1];
    const float* jup   = (const float*)d_in[2];
    const float* w     = (const float*)d_in[3];
    float* out = (float*)d_out;

    precompute_vqc<<<1, 32>>>(w);
    const int grid = (NB * 32) / THREADS;
    vqc_kernel<<<grid, THREADS>>>(theta, phi, jup, w, out);
}

// round 3
// speedup vs baseline: 1.2312x; 1.1179x over previous
#include <cuda_runtime.h>
#include <stdint.h>

#define NQ      8
#define NPAIRS  28
#define NB      16384
#define THREADS 128

typedef unsigned long long u64;

// batch-shared precomputed constants
__device__ float2 g_vqc_cs[2 * NQ];   // cos/sin(theta_w/2) per (layer,qubit)
__device__ float  g_hw[4][NQ];        // 0.5*phi_w(l0), 0.5*omega_w(l0), 0.5*phi_w(l1), 0.5*omega_w(l1)

__global__ void precompute_vqc(const float* __restrict__ w) {
    int i = threadIdx.x;
    if (i < 2 * NQ) {
        float th = w[i * 3 + 1];
        float c, s;
        __sincosf(0.5f * th, &s, &c);
        g_vqc_cs[i] = make_float2(c, s);
    }
    if (i < NQ) {
        g_hw[0][i] = 0.5f * w[i * 3 + 0];
        g_hw[1][i] = 0.5f * w[i * 3 + 2];
        g_hw[2][i] = 0.5f * w[(NQ + i) * 3 + 0];
        g_hw[3][i] = 0.5f * w[(NQ + i) * 3 + 2];
    }
}

// ---------------- f32x2 packed helpers ----------------
__device__ __forceinline__ u64 pk(float lo, float hi) {
    u64 v; asm("mov.b64 %0, {%1, %2};" : "=l"(v) : "f"(lo), "f"(hi)); return v;
}
__device__ __forceinline__ void upk(u64 v, float& lo, float& hi) {
    asm("mov.b64 {%0, %1}, %2;" : "=f"(lo), "=f"(hi) : "l"(v));
}
__device__ __forceinline__ u64 bc2(float x) { return pk(x, x); }
__device__ __forceinline__ u64 fma2(u64 a, u64 b, u64 c) {
    u64 d; asm("fma.rn.f32x2 %0, %1, %2, %3;" : "=l"(d) : "l"(a), "l"(b), "l"(c)); return d;
}
__device__ __forceinline__ u64 mul2(u64 a, u64 b) {
    u64 d; asm("mul.rn.f32x2 %0, %1, %2;" : "=l"(d) : "l"(a), "l"(b)); return d;
}
__device__ __forceinline__ u64 shflx2(u64 v, int m) {
    float lo, hi; upk(v, lo, hi);
    lo = __shfl_xor_sync(0xffffffffu, lo, m);
    hi = __shfl_xor_sync(0xffffffffu, hi, m);
    return pk(lo, hi);
}
__device__ __forceinline__ u64 shfli2(u64 v, int src) {
    float lo, hi; upk(v, lo, hi);
    lo = __shfl_sync(0xffffffffu, lo, src);
    hi = __shfl_sync(0xffffffffu, hi, src);
    return pk(lo, hi);
}

// ---------------- gate primitives ----------------
// State: s = lane*8 + r. Qubit k -> bit position bp = 7-k of s.
// bp in [3,7]: lane bit (bp-3); bp in [0,2]: register-index bit of r.

template<int K>
__device__ __forceinline__ void ry_gate(u64 (&a)[8], float c, float s, unsigned lane) {
    constexpr int bp = 7 - K;
    const u64 c2 = bc2(c);
    if constexpr (bp >= 3) {
        constexpr int lm = 1 << (bp - 3);
        const u64 sg2 = bc2((lane & lm) ? s : -s);
#pragma unroll
        for (int r = 0; r < 8; r++) {
            u64 p = shflx2(a[r], lm);
            a[r] = fma2(sg2, p, mul2(c2, a[r]));
        }
    } else {
        constexpr int m = 1 << bp;
        const u64 s2 = bc2(s), ns2 = bc2(-s);
#pragma unroll
        for (int r = 0; r < 8; r++) {
            if (!(r & m)) {
                u64 x = a[r], y = a[r | m];
                a[r]     = fma2(ns2, y, mul2(c2, x));
                a[r | m] = fma2(s2,  x, mul2(c2, y));
            }
        }
    }
}

template<int K>
__device__ __forceinline__ void ry_all(u64 (&a)[8], const float (&c)[8],
                                       const float (&s)[8], unsigned lane) {
    if constexpr (K < 8) {
        ry_gate<K>(a, c[K], s[K], lane);
        ry_all<K + 1>(a, c, s, lane);
    }
}

template<int CTRL, int TGT>
__device__ __forceinline__ void cnot_gate(u64 (&a)[8], unsigned lane) {
    constexpr int CB = 7 - CTRL, TB = 7 - TGT;
    if constexpr (TB >= 3) {
        constexpr int lm = 1 << (TB - 3);
        if constexpr (CB >= 3) {
            const int src = (int)(lane ^ (((lane >> (CB - 3)) & 1u) ? lm : 0u));
#pragma unroll
            for (int r = 0; r < 8; r++) a[r] = shfli2(a[r], src);
        } else {
#pragma unroll
            for (int r = 0; r < 8; r++)
                if ((r >> CB) & 1) a[r] = shflx2(a[r], lm);
        }
    } else {
        constexpr int m = 1 << TB;
        if constexpr (CB >= 3) {
            const bool cs = (lane >> (CB - 3)) & 1;
#pragma unroll
            for (int r = 0; r < 8; r++) {
                if (!(r & m)) {
                    u64 t0 = a[r], t1 = a[r | m];
                    a[r]     = cs ? t1 : t0;
                    a[r | m] = cs ? t0 : t1;
                }
            }
        } else {
#pragma unroll
            for (int r = 0; r < 8; r++) {
                if (((r >> CB) & 1) && !((r >> TB) & 1)) {
                    u64 t = a[r]; a[r] = a[r | m]; a[r | m] = t;
                }
            }
        }
    }
}

// apply a precomputed lane permutation (composition of lane-lane CNOTs)
__device__ __forceinline__ void lane_perm(u64 (&a)[8], int src) {
#pragma unroll
    for (int r = 0; r < 8; r++) a[r] = shfli2(a[r], src);
}

// Merged diagonal. phase(s) = sum_k (bit_k(s)? +hc[k] : -hc[k])
// Reg-bit part via 3-stage Walsh-Hadamard butterfly over r-bits.
__device__ __forceinline__ void diag_gate(u64 (&a)[8], const float (&hc)[8], unsigned lane) {
    float base = 0.f;
#pragma unroll
    for (int k = 0; k < 5; k++)
        base += ((lane >> (4 - k)) & 1) ? hc[k] : -hc[k];
    float w0[8] = { base, -hc[7], -hc[6], 0.f, -hc[5], 0.f, 0.f, 0.f };
#pragma unroll
    for (int st = 1; st < 8; st <<= 1) {
#pragma unroll
        for (int i = 0; i < 8; i++) {
            if (!(i & st)) {
                float u = w0[i], v = w0[i | st];
                w0[i] = u + v; w0[i | st] = u - v;
            }
        }
    }
#pragma unroll
    for (int r = 0; r < 8; r++) {
        float phr = w0[r];
        float q = rintf(phr * 0.15915494309189535f);
        phr = fmaf(q, -6.2831855f, phr);
        float cc, ss;
        __sincosf(phr, &ss, &cc);
        float x, y; upk(a[r], x, y);
        a[r] = pk(fmaf(cc, x, -ss * y), fmaf(cc, y, ss * x));
    }
}

// ---------------- main kernel ----------------

__global__ void __launch_bounds__(THREADS)
vqc_kernel(const float* __restrict__ theta, const float* __restrict__ phi,
           const float* __restrict__ jup, const float* __restrict__ w,
           float* __restrict__ out) {
    const unsigned tid  = blockIdx.x * THREADS + threadIdx.x;
    const unsigned b    = tid >> 5;
    const unsigned lane = tid & 31;

    float ph[NQ];
    float cq[NQ], sq[NQ];   // cos/sin(theta/4)  (re-encode round)
    float ch[NQ], sh[NQ];   // cos/sin(theta/2)  (encoding) via double-angle
#pragma unroll
    for (int k = 0; k < NQ; k++) {
        float th = theta[b * NQ + k];
        ph[k] = phi[b * NQ + k];
        __sincosf(0.25f * th, &sq[k], &cq[k]);
        sh[k] = 2.f * sq[k] * cq[k];
        ch[k] = fmaf(-2.f * sq[k], sq[k], 1.f);
    }

    // ===== Ising Walsh table over reg bits (lane part folded into index 0) =====
    float exr[8];
    {
        const float HP = 1.5707963267948966f;
        float il = 0.f, U0 = 0.f, U1 = 0.f, U2 = 0.f;
        float J56 = 0.f, J57 = 0.f, J67 = 0.f;
        int p = 0;
#pragma unroll
        for (int i = 0; i < 8; i++) {
#pragma unroll
            for (int j = i + 1; j < 8; j++) {
                float J = jup[(size_t)b * NPAIRS + p];
                if (j < 5) {
                    int d = ((lane >> (4 - i)) ^ (lane >> (4 - j))) & 1;
                    il += d ? J : -J;
                } else if (i < 5) {
                    int bi = (lane >> (4 - i)) & 1;
                    float v = bi ? J : -J;
                    if (j == 5) U0 += v; else if (j == 6) U1 += v; else U2 += v;
                } else {
                    if (i == 5 && j == 6) J56 = J;
                    else if (i == 5 && j == 7) J57 = J;
                    else J67 = J;
                }
                p++;
            }
        }
        exr[0] = il * HP;  exr[1] = U2 * HP;   exr[2] = U1 * HP;  exr[3] = -J67 * HP;
        exr[4] = U0 * HP;  exr[5] = -J57 * HP; exr[6] = -J56 * HP; exr[7] = 0.f;
    }

    // ===== Fused: product state after encoding RY + DIAG1 phase =====
    // amp(s) = prod_k (bit_k ? sin : cos)(theta_k/2);  then multiply e^{i*phase}
    u64 a[8];
    {
        // DIAG1 half-coeffs: 0.5*phi + 0.5*phi_w(l0)
        float hc[8];
#pragma unroll
        for (int k = 0; k < NQ; k++) hc[k] = fmaf(0.5f, ph[k], g_hw[0][k]);
        float base = 0.f;
#pragma unroll
        for (int k = 0; k < 5; k++)
            base += ((lane >> (4 - k)) & 1) ? hc[k] : -hc[k];
        // Walsh coeffs for reg-bit phase + Ising
        float w0[8];
        w0[0] = base + exr[0]; w0[1] = exr[1] - hc[7]; w0[2] = exr[2] - hc[6]; w0[3] = exr[3];
        w0[4] = exr[4] - hc[5]; w0[5] = exr[5]; w0[6] = exr[6]; w0[7] = exr[7];
#pragma unroll
        for (int st = 1; st < 8; st <<= 1) {
#pragma unroll
            for (int i = 0; i < 8; i++) {
                if (!(i & st)) {
                    float u = w0[i], v = w0[i | st];
                    w0[i] = u + v; w0[i | st] = u - v;
                }
            }
        }
        // magnitude: lane factor * reg factor
        float lf = 1.f;
#pragma unroll
        for (int k = 0; k < 5; k++)
            lf *= ((lane >> (4 - k)) & 1) ? sh[k] : ch[k];
        float f56[4];
        f56[0] = ch[5] * ch[6]; f56[1] = ch[5] * sh[6];
        f56[2] = sh[5] * ch[6]; f56[3] = sh[5] * sh[6];
#pragma unroll
        for (int r = 0; r < 8; r++) {
            float v = lf * f56[r >> 1] * ((r & 1) ? sh[7] : ch[7]);
            float phr = w0[r];
            float q = rintf(phr * 0.15915494309189535f);
            phr = fmaf(q, -6.2831855f, phr);
            float cc, ss;
            __sincosf(phr, &ss, &cc);
            a[r] = pk(v * cc, v * ss);
        }
    }

    // ===== layer 0 Rot-RY =====
    {
        float c[8], s[8];
#pragma unroll
        for (int k = 0; k < NQ; k++) { float2 cs = g_vqc_cs[k]; c[k] = cs.x; s[k] = cs.y; }
        ry_all<0>(a, c, s, lane);
    }
    // DIAG2: layer0 Rot-RZ(omega)
    {
        float hc[8];
#pragma unroll
        for (int k = 0; k < NQ; k++) hc[k] = g_hw[1][k];
        diag_gate(a, hc, lane);
    }
    // ===== CNOT ring 1: (0,1)(1,2)(2,3)(3,4) composed, then (4,5)(5,6)(6,7)(7,0) =====
    {
        // composed gather: src = g1(g2(g3(g4(lane))))
        unsigned t = lane;
        t ^= (t >> 1) & 1u;              // (3,4): ctrl lbit1 -> tgt lbit0
        t ^= ((t >> 2) & 1u) << 1;       // (2,3): ctrl lbit2 -> tgt lbit1
        t ^= ((t >> 3) & 1u) << 2;       // (1,2): ctrl lbit3 -> tgt lbit2
        t ^= ((t >> 4) & 1u) << 3;       // (0,1): ctrl lbit4 -> tgt lbit3
        lane_perm(a, (int)t);
    }
    cnot_gate<4, 5>(a, lane);
    cnot_gate<5, 6>(a, lane);
    cnot_gate<6, 7>(a, lane);
    cnot_gate<7, 0>(a, lane);

    // ===== re-encode RY(theta/2) =====
    ry_all<0>(a, cq, sq, lane);

    // DIAG3: re-encode RZ(phi/2) + layer1 Rot-RZ(phi_w)
    {
        float hc[8];
#pragma unroll
        for (int k = 0; k < NQ; k++) hc[k] = fmaf(0.25f, ph[k], g_hw[2][k]);
        diag_gate(a, hc, lane);
    }

    // ===== layer 1 Rot-RY =====
    {
        float c[8], s[8];
#pragma unroll
        for (int k = 0; k < NQ; k++) { float2 cs = g_vqc_cs[NQ + k]; c[k] = cs.x; s[k] = cs.y; }
        ry_all<0>(a, c, s, lane);
    }
    // DIAG4: layer1 Rot-RZ(omega)
    {
        float hc[8];
#pragma unroll
        for (int k = 0; k < NQ; k++) hc[k] = g_hw[3][k];
        diag_gate(a, hc, lane);
    }
    // ===== CNOT ring 2: (0,2)(1,3)(2,4) composed, then (3,5)(4,6)(5,7)(6,0)(7,1) =====
    {
        unsigned t = lane;
        t ^= (t >> 2) & 1u;              // (2,4): ctrl lbit2 -> tgt lbit0
        t ^= ((t >> 3) & 1u) << 1;       // (1,3): ctrl lbit3 -> tgt lbit1
        t ^= ((t >> 4) & 1u) << 2;       // (0,2): ctrl lbit4 -> tgt lbit2
        lane_perm(a, (int)t);
    }
    cnot_gate<3, 5>(a, lane);
    cnot_gate<4, 6>(a, lane);
    cnot_gate<5, 7>(a, lane);
    cnot_gate<6, 0>(a, lane);
    cnot_gate<7, 1>(a, lane);

    // ===== expectations =====
    float pw[8];
#pragma unroll
    for (int r = 0; r < 8; r++) {
        float x, y; upk(a[r], x, y);
        pw[r] = fmaf(x, x, y * y);
    }
#pragma unroll
    for (int st = 1; st < 8; st <<= 1) {
#pragma unroll
        for (int i = 0; i < 8; i++) {
            if (!(i & st)) {
                float u = pw[i], v = pw[i | st];
                pw[i] = u + v; pw[i | st] = u - v;
            }
        }
    }
    float ptot = pw[0], s5 = pw[4], s6 = pw[2], s7 = pw[1];

    // lane WHT on ptot: lane 2^(4-k) ends holding <Z_k> for k<5
#pragma unroll
    for (int m = 1; m < 32; m <<= 1) {
        float t = __shfl_xor_sync(0xffffffffu, ptot, m);
        ptot = (lane & m) ? (t - ptot) : (ptot + t);
    }
#pragma unroll
    for (int m = 1; m < 32; m <<= 1) {
        s5 += __shfl_xor_sync(0xffffffffu, s5, m);
        s6 += __shfl_xor_sync(0xffffffffu, s6, m);
        s7 += __shfl_xor_sync(0xffffffffu, s7, m);
    }

    float* ob = out + (size_t)b * NQ;
    if (__popc(lane) == 1 && lane <= 16)
        ob[5 - __ffs(lane)] = ptot;           // lanes 16,8,4,2,1 -> ez[0..4]
    if (lane == 0) { ob[5] = s5; ob[6] = s6; ob[7] = s7; }
}

extern "C" void kernel_launch(void* const* d_in, const int* in_sizes, int n_in,
                              void* d_out, int out_size) {
    const float* theta = (const float*)d_in[0];
    const float* phi   = (const float*)d_in[1];
    const float* jup   = (const float*)d_in[2];
    const float* w     = (const float*)d_in[3];
    float* out = (float*)d_out;

    precompute_vqc<<<1, 32>>>(w);
    const int grid = (NB * 32) / THREADS;
    vqc_kernel<<<grid, THREADS>>>(theta, phi, jup, w, out);
}